// round 4
// baseline (speedup 1.0000x reference)
#include <cuda_runtime.h>
#include <math.h>

namespace {

constexpr int B    = 4;
constexpr int S    = 2048;
constexpr int DIN  = 1024;
constexpr int DOUT = 1024;
constexpr int NH   = 16;
constexpr int HD   = 64;
constexpr int M    = B * S;            // 8192 rows

// ---- scratch (static device memory: allowed) ----
__device__ float g_q[(size_t)B * NH * S * HD];    // [B,H,S,HD]
__device__ float g_k[(size_t)B * NH * S * HD];
__device__ float g_v[(size_t)B * NH * S * HD];
__device__ float g_ctx[(size_t)M * DOUT];         // [B*S, DOUT]

__device__ __forceinline__ unsigned f2tf32(float x) {
    unsigned u;
    asm("cvt.rna.tf32.f32 %0, %1;" : "=r"(u) : "f"(x));
    return u;
}
__device__ __forceinline__ float tf(float x) { return __uint_as_float(f2tf32(x)); }

__device__ __forceinline__ void mma_tf32(
    float& c0, float& c1, float& c2, float& c3,
    unsigned a0, unsigned a1, unsigned a2, unsigned a3,
    unsigned b0, unsigned b1)
{
    asm volatile(
        "mma.sync.aligned.m16n8k8.row.col.f32.tf32.tf32.f32 "
        "{%0,%1,%2,%3}, {%4,%5,%6,%7}, {%8,%9}, {%0,%1,%2,%3};"
        : "+f"(c0), "+f"(c1), "+f"(c2), "+f"(c3)
        : "r"(a0), "r"(a1), "r"(a2), "r"(a3), "r"(b0), "r"(b1));
}

// ============================================================
// TF32 GEMM:  C[m,n] = sum_k A[m,k]*W[n,k] (+bias)
// Block tile 128x128, BK=32; 8 warps 4(m)x2(n), warp tile 32x64.
// Double-buffered smem, register prefetch of gmem tiles.
// ============================================================
constexpr int GBM = 128, GBN = 128, GBK = 32, GPAD = 36;
constexpr size_t GEMM_SMEM = (size_t)(2 * GBM * GPAD + 2 * GBN * GPAD) * sizeof(float); // 73728

__global__ __launch_bounds__(256) void gemm_tf32_kernel(
    const float* __restrict__ A, const float* __restrict__ W,
    float* __restrict__ C, const float* __restrict__ bias,
    int K, int N, int head_layout)
{
    extern __shared__ float sm[];
    float* sA = sm;                       // [2][128][36]
    float* sW = sm + 2 * GBM * GPAD;      // [2][128][36]

    const int tid  = threadIdx.x;
    const int m0   = blockIdx.y * GBM;
    const int n0   = blockIdx.x * GBN;
    const int warp = tid >> 5, lane = tid & 31;
    const int wm = (warp >> 1) * 32;      // 0,32,64,96
    const int wn = (warp & 1) * 64;       // 0,64
    const int lr = lane >> 2, lc = lane & 3;

    float4 ra[4], rw[4];

    auto load_tile = [&](int k0) {
#pragma unroll
        for (int p = 0; p < 4; p++) {
            int idx = p * 256 + tid;
            int row = idx >> 3, c4 = (idx & 7) << 2;
            ra[p] = *reinterpret_cast<const float4*>(A + (size_t)(m0 + row) * K + k0 + c4);
            rw[p] = *reinterpret_cast<const float4*>(W + (size_t)(n0 + row) * K + k0 + c4);
        }
    };
    auto store_tile = [&](int buf) {
        float* dA = sA + buf * GBM * GPAD;
        float* dW = sW + buf * GBN * GPAD;
#pragma unroll
        for (int p = 0; p < 4; p++) {
            int idx = p * 256 + tid;
            int row = idx >> 3, c4 = (idx & 7) << 2;
            dA[row * GPAD + c4 + 0] = tf(ra[p].x);
            dA[row * GPAD + c4 + 1] = tf(ra[p].y);
            dA[row * GPAD + c4 + 2] = tf(ra[p].z);
            dA[row * GPAD + c4 + 3] = tf(ra[p].w);
            dW[row * GPAD + c4 + 0] = tf(rw[p].x);
            dW[row * GPAD + c4 + 1] = tf(rw[p].y);
            dW[row * GPAD + c4 + 2] = tf(rw[p].z);
            dW[row * GPAD + c4 + 3] = tf(rw[p].w);
        }
    };

    float acc[2][8][4] = {};

    load_tile(0);
    store_tile(0);
    const int NIT = K / GBK;
    for (int it = 0; it < NIT; ++it) {
        __syncthreads();
        if (it + 1 < NIT) load_tile((it + 1) * GBK);

        const float* bA = sA + (it & 1) * GBM * GPAD;
        const float* bW = sW + (it & 1) * GBN * GPAD;
#pragma unroll
        for (int kk = 0; kk < GBK; kk += 8) {
            unsigned af[2][4], bf[8][2];
#pragma unroll
            for (int mt = 0; mt < 2; mt++) {
                int r = wm + mt * 16 + lr;
                af[mt][0] = __float_as_uint(bA[r * GPAD + kk + lc]);
                af[mt][1] = __float_as_uint(bA[(r + 8) * GPAD + kk + lc]);
                af[mt][2] = __float_as_uint(bA[r * GPAD + kk + lc + 4]);
                af[mt][3] = __float_as_uint(bA[(r + 8) * GPAD + kk + lc + 4]);
            }
#pragma unroll
            for (int nt = 0; nt < 8; nt++) {
                int c = wn + nt * 8 + lr;
                bf[nt][0] = __float_as_uint(bW[c * GPAD + kk + lc]);
                bf[nt][1] = __float_as_uint(bW[c * GPAD + kk + lc + 4]);
            }
#pragma unroll
            for (int mt = 0; mt < 2; mt++)
#pragma unroll
                for (int nt = 0; nt < 8; nt++)
                    mma_tf32(acc[mt][nt][0], acc[mt][nt][1], acc[mt][nt][2], acc[mt][nt][3],
                             af[mt][0], af[mt][1], af[mt][2], af[mt][3],
                             bf[nt][0], bf[nt][1]);
        }
        if (it + 1 < NIT) store_tile((it + 1) & 1);
    }

#pragma unroll
    for (int mt = 0; mt < 2; mt++) {
#pragma unroll
        for (int i = 0; i < 2; i++) {
            int m = m0 + wm + mt * 16 + lr + i * 8;
#pragma unroll
            for (int nt = 0; nt < 8; nt++) {
                int n = n0 + wn + nt * 8 + lc * 2;
                float v0 = acc[mt][nt][i * 2 + 0];
                float v1 = acc[mt][nt][i * 2 + 1];
                if (bias) { v0 += bias[n]; v1 += bias[n + 1]; }
                if (!head_layout) {
                    *reinterpret_cast<float2*>(&C[(size_t)m * N + n]) = make_float2(v0, v1);
                } else {
                    int h = n >> 6, d = n & 63;
                    int bb = m >> 11, ss = m & 2047;
                    *reinterpret_cast<float2*>(
                        &C[(((size_t)(bb * NH + h) * S) + ss) * HD + d]) = make_float2(v0, v1);
                }
            }
        }
    }
}

// ============================================================
// Causal flash attention, tf32 mma, double-buffered K/V tiles.
// 8 warps 4(m)x2(n) over the 64x64 tile; fp32 online softmax.
// ============================================================
constexpr int BQ  = 64;
constexpr int BKV = 64;
constexpr int PAD = 68;
constexpr int ATILE = BQ * PAD;                  // one 64-row tile
constexpr size_t ATTN_SMEM = (size_t)6 * ATILE * sizeof(float);  // Q + 2K + 2V + P

__global__ __launch_bounds__(256) void attn_kernel(
    const float* __restrict__ Q, const float* __restrict__ Kp,
    const float* __restrict__ Vp, float* __restrict__ ctx)
{
    extern __shared__ float sm[];
    float (*Qs)[PAD] = reinterpret_cast<float(*)[PAD]>(sm);
    float (*Ps)[PAD] = reinterpret_cast<float(*)[PAD]>(sm + 5 * ATILE);

    __shared__ float m_s[BQ], l_s[BQ], alpha_s[BQ];

    const int tid  = threadIdx.x;
    const int warp = tid >> 5, lane = tid & 31;
    const int wm = (warp >> 1) * 16;
    const int wn = (warp & 1) * 32;
    const int lr = lane >> 2, lc = lane & 3;
    const int qt = blockIdx.x;
    const int bh = blockIdx.y;

    const float* qb = Q  + (size_t)bh * S * HD + (size_t)qt * BQ * HD;
    const float* kb = Kp + (size_t)bh * S * HD;
    const float* vb = Vp + (size_t)bh * S * HD;

    float4 rk[4], rv[4];
    auto load_kv = [&](int kt) {
        const float* kp_ = kb + (size_t)kt * BKV * HD;
        const float* vp_ = vb + (size_t)kt * BKV * HD;
#pragma unroll
        for (int p = 0; p < 4; p++) {
            int idx = p * 256 + tid;
            int row = idx >> 4, c4 = (idx & 15) << 2;
            rk[p] = *reinterpret_cast<const float4*>(kp_ + row * HD + c4);
            rv[p] = *reinterpret_cast<const float4*>(vp_ + row * HD + c4);
        }
    };
    auto store_kv = [&](int buf) {
        float* K_ = sm + (1 + buf) * ATILE;
        float* V_ = sm + (3 + buf) * ATILE;
#pragma unroll
        for (int p = 0; p < 4; p++) {
            int idx = p * 256 + tid;
            int row = idx >> 4, c4 = (idx & 15) << 2;
            K_[row * PAD + c4 + 0] = tf(rk[p].x);
            K_[row * PAD + c4 + 1] = tf(rk[p].y);
            K_[row * PAD + c4 + 2] = tf(rk[p].z);
            K_[row * PAD + c4 + 3] = tf(rk[p].w);
            V_[row * PAD + c4 + 0] = tf(rv[p].x);
            V_[row * PAD + c4 + 1] = tf(rv[p].y);
            V_[row * PAD + c4 + 2] = tf(rv[p].z);
            V_[row * PAD + c4 + 3] = tf(rv[p].w);
        }
    };

    // load Q tile: fold softmax scale, convert to tf32
    for (int i = tid; i < BQ * HD / 4; i += 256) {
        int row = i >> 4;
        int c4  = (i & 15) << 2;
        float4 v = *reinterpret_cast<const float4*>(qb + row * HD + c4);
        Qs[row][c4 + 0] = tf(v.x * 0.125f);
        Qs[row][c4 + 1] = tf(v.y * 0.125f);
        Qs[row][c4 + 2] = tf(v.z * 0.125f);
        Qs[row][c4 + 3] = tf(v.w * 0.125f);
    }
    if (tid < BQ) { m_s[tid] = -1e30f; l_s[tid] = 0.f; }

    load_kv(0);
    store_kv(0);

    float acc_o[4][4] = {};
    __syncthreads();

    for (int kt = 0; kt <= qt; kt++) {
        const int cur = kt & 1;
        const bool more = (kt < qt);
        if (more) load_kv(kt + 1);          // prefetch next tile into regs

        const float (*Ksc)[PAD] = reinterpret_cast<const float(*)[PAD]>(sm + (1 + cur) * ATILE);
        const float (*Vsc)[PAD] = reinterpret_cast<const float(*)[PAD]>(sm + (3 + cur) * ATILE);

        // ---- scores: S = Qs @ Ks^T ----
        float acc_s[4][4] = {};
#pragma unroll
        for (int kk = 0; kk < HD; kk += 8) {
            unsigned a0 = __float_as_uint(Qs[wm + lr][kk + lc]);
            unsigned a1 = __float_as_uint(Qs[wm + lr + 8][kk + lc]);
            unsigned a2 = __float_as_uint(Qs[wm + lr][kk + lc + 4]);
            unsigned a3 = __float_as_uint(Qs[wm + lr + 8][kk + lc + 4]);
#pragma unroll
            for (int nt = 0; nt < 4; nt++) {
                int c = wn + nt * 8 + lr;
                unsigned b0 = __float_as_uint(Ksc[c][kk + lc]);
                unsigned b1 = __float_as_uint(Ksc[c][kk + lc + 4]);
                mma_tf32(acc_s[nt][0], acc_s[nt][1], acc_s[nt][2], acc_s[nt][3],
                         a0, a1, a2, a3, b0, b1);
            }
        }
#pragma unroll
        for (int nt = 0; nt < 4; nt++) {
            int c = wn + nt * 8 + lc * 2;
            *reinterpret_cast<float2*>(&Ps[wm + lr][c])     = make_float2(acc_s[nt][0], acc_s[nt][1]);
            *reinterpret_cast<float2*>(&Ps[wm + lr + 8][c]) = make_float2(acc_s[nt][2], acc_s[nt][3]);
        }
        // overlap: write prefetched K/V into the other buffer while waiting
        if (more) store_kv(1 - cur);
        __syncthreads();

        // ---- online softmax: 4 threads/row ----
        {
            int r = tid >> 2;
            int part = tid & 3;
            bool diag = (kt == qt);
            float vals[16];
#pragma unroll
            for (int j = 0; j < 16; j++) {
                int col = part * 16 + j;
                float v = Ps[r][col];
                if (diag && col > r) v = -1e30f;
                vals[j] = v;
            }
            float m_old = m_s[r];
            float mx = m_old;
#pragma unroll
            for (int j = 0; j < 16; j++) mx = fmaxf(mx, vals[j]);
            mx = fmaxf(mx, __shfl_xor_sync(0xffffffffu, mx, 1));
            mx = fmaxf(mx, __shfl_xor_sync(0xffffffffu, mx, 2));
            float sum = 0.f;
#pragma unroll
            for (int j = 0; j < 16; j++) {
                float p = tf(__expf(vals[j] - mx));
                Ps[r][part * 16 + j] = p;
                sum += p;
            }
            sum += __shfl_xor_sync(0xffffffffu, sum, 1);
            sum += __shfl_xor_sync(0xffffffffu, sum, 2);
            if (part == 0) {
                float alpha = __expf(m_old - mx);
                l_s[r] = l_s[r] * alpha + sum;
                m_s[r] = mx;
                alpha_s[r] = alpha;
            }
        }
        __syncthreads();

        // ---- rescale O, then O += P @ V ----
        {
            float al0 = alpha_s[wm + lr];
            float al1 = alpha_s[wm + lr + 8];
#pragma unroll
            for (int nt = 0; nt < 4; nt++) {
                acc_o[nt][0] *= al0; acc_o[nt][1] *= al0;
                acc_o[nt][2] *= al1; acc_o[nt][3] *= al1;
            }
        }
#pragma unroll
        for (int kk = 0; kk < BKV; kk += 8) {
            unsigned a0 = __float_as_uint(Ps[wm + lr][kk + lc]);
            unsigned a1 = __float_as_uint(Ps[wm + lr + 8][kk + lc]);
            unsigned a2 = __float_as_uint(Ps[wm + lr][kk + lc + 4]);
            unsigned a3 = __float_as_uint(Ps[wm + lr + 8][kk + lc + 4]);
#pragma unroll
            for (int nt = 0; nt < 4; nt++) {
                int c = wn + nt * 8 + lr;
                unsigned b0 = __float_as_uint(Vsc[kk + lc][c]);
                unsigned b1 = __float_as_uint(Vsc[kk + lc + 4][c]);
                mma_tf32(acc_o[nt][0], acc_o[nt][1], acc_o[nt][2], acc_o[nt][3],
                         a0, a1, a2, a3, b0, b1);
            }
        }
        __syncthreads();   // Ps reusable + next-buffer stores visible
    }

    // epilogue: normalize, write ctx
    const int h  = bh % NH;
    const int bb = bh / NH;
    {
        int r0 = wm + lr, r1 = wm + lr + 8;
        float inv0 = 1.0f / l_s[r0];
        float inv1 = 1.0f / l_s[r1];
        size_t row0 = (size_t)(bb * S + qt * BQ + r0) * DOUT + h * HD;
        size_t row1 = (size_t)(bb * S + qt * BQ + r1) * DOUT + h * HD;
#pragma unroll
        for (int nt = 0; nt < 4; nt++) {
            int c = wn + nt * 8 + lc * 2;
            *reinterpret_cast<float2*>(&ctx[row0 + c]) =
                make_float2(acc_o[nt][0] * inv0, acc_o[nt][1] * inv0);
            *reinterpret_cast<float2*>(&ctx[row1 + c]) =
                make_float2(acc_o[nt][2] * inv1, acc_o[nt][3] * inv1);
        }
    }
}

}  // namespace

extern "C" void kernel_launch(void* const* d_in, const int* in_sizes, int n_in,
                              void* d_out, int out_size)
{
    (void)in_sizes; (void)n_in; (void)out_size;
    const float* x  = (const float*)d_in[0];
    const float* Wq = (const float*)d_in[1];
    const float* Wk = (const float*)d_in[2];
    const float* Wv = (const float*)d_in[3];
    const float* Wo = (const float*)d_in[4];
    const float* bo = (const float*)d_in[5];
    float* out = (float*)d_out;

    float *qp, *kp, *vp, *cp;
    cudaGetSymbolAddress((void**)&qp, g_q);
    cudaGetSymbolAddress((void**)&kp, g_k);
    cudaGetSymbolAddress((void**)&vp, g_v);
    cudaGetSymbolAddress((void**)&cp, g_ctx);

    cudaFuncSetAttribute(gemm_tf32_kernel,
                         cudaFuncAttributeMaxDynamicSharedMemorySize,
                         (int)GEMM_SMEM);
    cudaFuncSetAttribute(attn_kernel,
                         cudaFuncAttributeMaxDynamicSharedMemorySize,
                         (int)ATTN_SMEM);

    dim3 gemm_grid(DOUT / GBN, M / GBM);   // (8, 64)

    gemm_tf32_kernel<<<gemm_grid, 256, GEMM_SMEM>>>(x, Wq, qp, nullptr, DIN, DOUT, 1);
    gemm_tf32_kernel<<<gemm_grid, 256, GEMM_SMEM>>>(x, Wk, kp, nullptr, DIN, DOUT, 1);
    gemm_tf32_kernel<<<gemm_grid, 256, GEMM_SMEM>>>(x, Wv, vp, nullptr, DIN, DOUT, 1);

    dim3 attn_grid(S / BQ, B * NH);        // (32, 64)
    attn_kernel<<<attn_grid, 256, ATTN_SMEM>>>(qp, kp, vp, cp);

    gemm_tf32_kernel<<<gemm_grid, 256, GEMM_SMEM>>>(cp, Wo, out, bo, DOUT, DOUT, 0);
}

// round 5
// speedup vs baseline: 1.7024x; 1.7024x over previous
#include <cuda_runtime.h>
#include <math.h>

namespace {

constexpr int B    = 4;
constexpr int S    = 2048;
constexpr int DIN  = 1024;
constexpr int DOUT = 1024;
constexpr int NH   = 16;
constexpr int HD   = 64;
constexpr int M    = B * S;            // 8192 rows

// ---- scratch (static device memory: allowed) ----
__device__ float g_q[(size_t)B * NH * S * HD];    // [B,H,S,HD]
__device__ float g_k[(size_t)B * NH * S * HD];
__device__ float g_v[(size_t)B * NH * S * HD];
__device__ float g_ctx[(size_t)M * DOUT];         // [B*S, DOUT]

__device__ __forceinline__ unsigned f2tf32(float x) {
    unsigned u;
    asm("cvt.rna.tf32.f32 %0, %1;" : "=r"(u) : "f"(x));
    return u;
}
__device__ __forceinline__ float tf(float x) { return __uint_as_float(f2tf32(x)); }

__device__ __forceinline__ void mma_tf32(
    float& c0, float& c1, float& c2, float& c3,
    unsigned a0, unsigned a1, unsigned a2, unsigned a3,
    unsigned b0, unsigned b1)
{
    asm volatile(
        "mma.sync.aligned.m16n8k8.row.col.f32.tf32.tf32.f32 "
        "{%0,%1,%2,%3}, {%4,%5,%6,%7}, {%8,%9}, {%0,%1,%2,%3};"
        : "+f"(c0), "+f"(c1), "+f"(c2), "+f"(c3)
        : "r"(a0), "r"(a1), "r"(a2), "r"(a3), "r"(b0), "r"(b1));
}

// ============================================================
// TF32 GEMM (exact round-3 version, known-good 624us for 4 calls)
// Block tile 128x64, BK=32; 8 warps 4(m)x2(n), warp tile 32x32.
// ============================================================
constexpr int GBM = 128, GBN = 64, GBK = 32, GPAD = 36;
constexpr size_t GEMM_SMEM = (size_t)(2 * GBM * GPAD + 2 * GBN * GPAD) * sizeof(float);

__global__ __launch_bounds__(256) void gemm_tf32_kernel(
    const float* __restrict__ A, const float* __restrict__ W,
    float* __restrict__ C, const float* __restrict__ bias,
    int K, int N, int head_layout)
{
    extern __shared__ float sm[];
    float* sA = sm;
    float* sW = sm + 2 * GBM * GPAD;

    const int tid  = threadIdx.x;
    const int m0   = blockIdx.y * GBM;
    const int n0   = blockIdx.x * GBN;
    const int warp = tid >> 5, lane = tid & 31;
    const int wm = (warp >> 1) * 32;
    const int wn = (warp & 1) * 32;
    const int lr = lane >> 2, lc = lane & 3;

    float4 ra[4], rw[2];

    auto load_tile = [&](int k0) {
#pragma unroll
        for (int p = 0; p < 4; p++) {
            int idx = p * 256 + tid;
            int row = idx >> 3, c4 = (idx & 7) << 2;
            ra[p] = *reinterpret_cast<const float4*>(A + (size_t)(m0 + row) * K + k0 + c4);
        }
#pragma unroll
        for (int p = 0; p < 2; p++) {
            int idx = p * 256 + tid;
            int row = idx >> 3, c4 = (idx & 7) << 2;
            rw[p] = *reinterpret_cast<const float4*>(W + (size_t)(n0 + row) * K + k0 + c4);
        }
    };
    auto store_tile = [&](int buf) {
        float* dA = sA + buf * GBM * GPAD;
        float* dW = sW + buf * GBN * GPAD;
#pragma unroll
        for (int p = 0; p < 4; p++) {
            int idx = p * 256 + tid;
            int row = idx >> 3, c4 = (idx & 7) << 2;
            dA[row * GPAD + c4 + 0] = tf(ra[p].x);
            dA[row * GPAD + c4 + 1] = tf(ra[p].y);
            dA[row * GPAD + c4 + 2] = tf(ra[p].z);
            dA[row * GPAD + c4 + 3] = tf(ra[p].w);
        }
#pragma unroll
        for (int p = 0; p < 2; p++) {
            int idx = p * 256 + tid;
            int row = idx >> 3, c4 = (idx & 7) << 2;
            dW[row * GPAD + c4 + 0] = tf(rw[p].x);
            dW[row * GPAD + c4 + 1] = tf(rw[p].y);
            dW[row * GPAD + c4 + 2] = tf(rw[p].z);
            dW[row * GPAD + c4 + 3] = tf(rw[p].w);
        }
    };

    float acc[2][4][4] = {};

    load_tile(0);
    store_tile(0);
    const int NIT = K / GBK;
    for (int it = 0; it < NIT; ++it) {
        __syncthreads();
        if (it + 1 < NIT) load_tile((it + 1) * GBK);

        const float* bA = sA + (it & 1) * GBM * GPAD;
        const float* bW = sW + (it & 1) * GBN * GPAD;
#pragma unroll
        for (int kk = 0; kk < GBK; kk += 8) {
            unsigned af[2][4], bf[4][2];
#pragma unroll
            for (int mt = 0; mt < 2; mt++) {
                int r = wm + mt * 16 + lr;
                af[mt][0] = __float_as_uint(bA[r * GPAD + kk + lc]);
                af[mt][1] = __float_as_uint(bA[(r + 8) * GPAD + kk + lc]);
                af[mt][2] = __float_as_uint(bA[r * GPAD + kk + lc + 4]);
                af[mt][3] = __float_as_uint(bA[(r + 8) * GPAD + kk + lc + 4]);
            }
#pragma unroll
            for (int nt = 0; nt < 4; nt++) {
                int c = wn + nt * 8 + lr;
                bf[nt][0] = __float_as_uint(bW[c * GPAD + kk + lc]);
                bf[nt][1] = __float_as_uint(bW[c * GPAD + kk + lc + 4]);
            }
#pragma unroll
            for (int mt = 0; mt < 2; mt++)
#pragma unroll
                for (int nt = 0; nt < 4; nt++)
                    mma_tf32(acc[mt][nt][0], acc[mt][nt][1], acc[mt][nt][2], acc[mt][nt][3],
                             af[mt][0], af[mt][1], af[mt][2], af[mt][3],
                             bf[nt][0], bf[nt][1]);
        }
        if (it + 1 < NIT) store_tile((it + 1) & 1);
    }

#pragma unroll
    for (int mt = 0; mt < 2; mt++) {
#pragma unroll
        for (int i = 0; i < 2; i++) {
            int m = m0 + wm + mt * 16 + lr + i * 8;
#pragma unroll
            for (int nt = 0; nt < 4; nt++) {
                int n = n0 + wn + nt * 8 + lc * 2;
                float v0 = acc[mt][nt][i * 2 + 0];
                float v1 = acc[mt][nt][i * 2 + 1];
                if (bias) { v0 += bias[n]; v1 += bias[n + 1]; }
                if (!head_layout) {
                    *reinterpret_cast<float2*>(&C[(size_t)m * N + n]) = make_float2(v0, v1);
                } else {
                    int h = n >> 6, d = n & 63;
                    int bb = m >> 11, ss = m & 2047;
                    *reinterpret_cast<float2*>(
                        &C[(((size_t)(bb * NH + h) * S) + ss) * HD + d]) = make_float2(v0, v1);
                }
            }
        }
    }
}

// ============================================================
// Causal flash attention: BQ=128, BKV=64, tf32 mma,
// in-register softmax (exp2 domain), single-buffered K/V.
// 8 warps: 4(m: 32 rows each) x 2(n: 32 cols each).
// ============================================================
constexpr int BQ  = 128;
constexpr int BKV = 64;
constexpr int PAD = 68;
constexpr float LOG2E = 1.4426950408889634f;
// Qs[128] Ks[64] Vs[64] Ps[128] rows, PAD floats each
constexpr size_t ATTN_SMEM = (size_t)(BQ + BKV + BKV + BQ) * PAD * sizeof(float); // 104448

__global__ __launch_bounds__(256) void attn_kernel(
    const float* __restrict__ Q, const float* __restrict__ Kp,
    const float* __restrict__ Vp, float* __restrict__ ctx)
{
    extern __shared__ float sm[];
    float (*Qs)[PAD] = reinterpret_cast<float(*)[PAD]>(sm);
    float (*Ks)[PAD] = reinterpret_cast<float(*)[PAD]>(sm + BQ * PAD);
    float (*Vs)[PAD] = reinterpret_cast<float(*)[PAD]>(sm + (BQ + BKV) * PAD);
    float (*Ps)[PAD] = reinterpret_cast<float(*)[PAD]>(sm + (BQ + 2 * BKV) * PAD);

    __shared__ float m_s[BQ], l_s[BQ];
    __shared__ float pmax[BQ][2], psum[BQ][2];

    const int tid  = threadIdx.x;
    const int warp = tid >> 5, lane = tid & 31;
    const int wm = (warp >> 1) * 32;      // 0,32,64,96
    const int wn = (warp & 1) * 32;       // 0,32
    const int wi = warp & 1;
    const int lr = lane >> 2, lc = lane & 3;
    const int qt = blockIdx.x;
    const int bh = blockIdx.y;

    const float* qb = Q  + (size_t)bh * S * HD + (size_t)qt * BQ * HD;
    const float* kb = Kp + (size_t)bh * S * HD;
    const float* vb = Vp + (size_t)bh * S * HD;

    // load Q tile: fold scale*log2e, convert to tf32
    const float qscale = 0.125f * LOG2E;
    for (int i = tid; i < BQ * HD / 4; i += 256) {
        int row = i >> 4;
        int c4  = (i & 15) << 2;
        float4 v = *reinterpret_cast<const float4*>(qb + row * HD + c4);
        Qs[row][c4 + 0] = tf(v.x * qscale);
        Qs[row][c4 + 1] = tf(v.y * qscale);
        Qs[row][c4 + 2] = tf(v.z * qscale);
        Qs[row][c4 + 3] = tf(v.w * qscale);
    }
    if (tid < BQ) { m_s[tid] = -1e30f; l_s[tid] = 0.f; }

    float acc_o[2][4][4] = {};
    __syncthreads();

    const int NKT = 2 * qt + 2;           // kv tiles 0 .. 2qt+1
    for (int kt = 0; kt < NKT; kt++) {
        // ---- load K/V tile (gmem -> smem, tf32) ----
        const float* kp_ = kb + (size_t)kt * BKV * HD;
        const float* vp_ = vb + (size_t)kt * BKV * HD;
        for (int i = tid; i < BKV * HD / 4; i += 256) {
            int row = i >> 4, c4 = (i & 15) << 2;
            float4 vk = *reinterpret_cast<const float4*>(kp_ + row * HD + c4);
            Ks[row][c4 + 0] = tf(vk.x); Ks[row][c4 + 1] = tf(vk.y);
            Ks[row][c4 + 2] = tf(vk.z); Ks[row][c4 + 3] = tf(vk.w);
            float4 vv = *reinterpret_cast<const float4*>(vp_ + row * HD + c4);
            Vs[row][c4 + 0] = tf(vv.x); Vs[row][c4 + 1] = tf(vv.y);
            Vs[row][c4 + 2] = tf(vv.z); Vs[row][c4 + 3] = tf(vv.w);
        }
        __syncthreads();                                   // sync 1

        // ---- scores: S = Qs @ Ks^T (2 m-tiles x 4 n-tiles) ----
        float acc_s[2][4][4] = {};
#pragma unroll
        for (int kk = 0; kk < HD; kk += 8) {
            unsigned af[2][4], bf[4][2];
#pragma unroll
            for (int mt = 0; mt < 2; mt++) {
                int r = wm + mt * 16 + lr;
                af[mt][0] = __float_as_uint(Qs[r][kk + lc]);
                af[mt][1] = __float_as_uint(Qs[r + 8][kk + lc]);
                af[mt][2] = __float_as_uint(Qs[r][kk + lc + 4]);
                af[mt][3] = __float_as_uint(Qs[r + 8][kk + lc + 4]);
            }
#pragma unroll
            for (int nt = 0; nt < 4; nt++) {
                int c = wn + nt * 8 + lr;
                bf[nt][0] = __float_as_uint(Ks[c][kk + lc]);
                bf[nt][1] = __float_as_uint(Ks[c][kk + lc + 4]);
            }
#pragma unroll
            for (int mt = 0; mt < 2; mt++)
#pragma unroll
                for (int nt = 0; nt < 4; nt++)
                    mma_tf32(acc_s[mt][nt][0], acc_s[mt][nt][1],
                             acc_s[mt][nt][2], acc_s[mt][nt][3],
                             af[mt][0], af[mt][1], af[mt][2], af[mt][3],
                             bf[nt][0], bf[nt][1]);
        }

        // ---- causal mask (in regs, only tiles that touch the diagonal) ----
        if (kt >= 2 * qt) {
            int cbase = kt * BKV - qt * BQ;   // col_global - row_tile_base
#pragma unroll
            for (int mt = 0; mt < 2; mt++) {
                int r0 = wm + mt * 16 + lr;
#pragma unroll
                for (int nt = 0; nt < 4; nt++) {
                    int c0 = cbase + wn + nt * 8 + 2 * lc;
                    if (c0 > r0)         acc_s[mt][nt][0] = -1e30f;
                    if (c0 + 1 > r0)     acc_s[mt][nt][1] = -1e30f;
                    if (c0 > r0 + 8)     acc_s[mt][nt][2] = -1e30f;
                    if (c0 + 1 > r0 + 8) acc_s[mt][nt][3] = -1e30f;
                }
            }
        }

        // ---- warp-local row max (quad shfl), publish per-warp partial ----
        float rmax[2][2];
#pragma unroll
        for (int mt = 0; mt < 2; mt++) {
            float m0 = -1e30f, m1 = -1e30f;
#pragma unroll
            for (int nt = 0; nt < 4; nt++) {
                m0 = fmaxf(m0, fmaxf(acc_s[mt][nt][0], acc_s[mt][nt][1]));
                m1 = fmaxf(m1, fmaxf(acc_s[mt][nt][2], acc_s[mt][nt][3]));
            }
            m0 = fmaxf(m0, __shfl_xor_sync(0xffffffffu, m0, 1));
            m0 = fmaxf(m0, __shfl_xor_sync(0xffffffffu, m0, 2));
            m1 = fmaxf(m1, __shfl_xor_sync(0xffffffffu, m1, 1));
            m1 = fmaxf(m1, __shfl_xor_sync(0xffffffffu, m1, 2));
            rmax[mt][0] = m0; rmax[mt][1] = m1;
            if (lc == 0) {
                pmax[wm + mt * 16 + lr][wi] = m0;
                pmax[wm + mt * 16 + lr + 8][wi] = m1;
            }
        }
        __syncthreads();                                   // sync 2

        // ---- mx/alpha, exp2 in regs, write tf32 P, partial sums ----
        float alpha[2][2], mxv[2][2], rsum[2][2];
#pragma unroll
        for (int mt = 0; mt < 2; mt++) {
#pragma unroll
            for (int i = 0; i < 2; i++) {
                int r = wm + mt * 16 + lr + i * 8;
                float mo = m_s[r];
                float mx = fmaxf(mo, fmaxf(pmax[r][0], pmax[r][1]));
                mxv[mt][i] = mx;
                alpha[mt][i] = exp2f(mo - mx);
                float sum = 0.f;
#pragma unroll
                for (int nt = 0; nt < 4; nt++) {
                    float p0 = tf(exp2f(acc_s[mt][nt][i * 2 + 0] - mx));
                    float p1 = tf(exp2f(acc_s[mt][nt][i * 2 + 1] - mx));
                    sum += p0 + p1;
                    *reinterpret_cast<float2*>(&Ps[r][wn + nt * 8 + 2 * lc]) =
                        make_float2(p0, p1);
                }
                sum += __shfl_xor_sync(0xffffffffu, sum, 1);
                sum += __shfl_xor_sync(0xffffffffu, sum, 2);
                rsum[mt][i] = sum;
                if (lc == 0) psum[r][wi] = sum;
            }
        }
        __syncthreads();                                   // sync 3

        // ---- state update (owner), rescale O, PV mma ----
        if (wi == 0 && lc == 0) {
#pragma unroll
            for (int mt = 0; mt < 2; mt++)
#pragma unroll
                for (int i = 0; i < 2; i++) {
                    int r = wm + mt * 16 + lr + i * 8;
                    l_s[r] = l_s[r] * alpha[mt][i] + psum[r][0] + psum[r][1];
                    m_s[r] = mxv[mt][i];
                }
        }
#pragma unroll
        for (int mt = 0; mt < 2; mt++)
#pragma unroll
            for (int nt = 0; nt < 4; nt++) {
                acc_o[mt][nt][0] *= alpha[mt][0]; acc_o[mt][nt][1] *= alpha[mt][0];
                acc_o[mt][nt][2] *= alpha[mt][1]; acc_o[mt][nt][3] *= alpha[mt][1];
            }
#pragma unroll
        for (int kk = 0; kk < BKV; kk += 8) {
            unsigned af[2][4], bf[4][2];
#pragma unroll
            for (int mt = 0; mt < 2; mt++) {
                int r = wm + mt * 16 + lr;
                af[mt][0] = __float_as_uint(Ps[r][kk + lc]);
                af[mt][1] = __float_as_uint(Ps[r + 8][kk + lc]);
                af[mt][2] = __float_as_uint(Ps[r][kk + lc + 4]);
                af[mt][3] = __float_as_uint(Ps[r + 8][kk + lc + 4]);
            }
#pragma unroll
            for (int nt = 0; nt < 4; nt++) {
                int c = wn + nt * 8 + lr;
                bf[nt][0] = __float_as_uint(Vs[kk + lc][c]);
                bf[nt][1] = __float_as_uint(Vs[kk + lc + 4][c]);
            }
#pragma unroll
            for (int mt = 0; mt < 2; mt++)
#pragma unroll
                for (int nt = 0; nt < 4; nt++)
                    mma_tf32(acc_o[mt][nt][0], acc_o[mt][nt][1],
                             acc_o[mt][nt][2], acc_o[mt][nt][3],
                             af[mt][0], af[mt][1], af[mt][2], af[mt][3],
                             bf[nt][0], bf[nt][1]);
        }
        __syncthreads();                                   // sync 4
    }

    // ---- epilogue: normalize, write ctx [B*S, DOUT] at col h*HD+d ----
    const int h  = bh % NH;
    const int bb = bh / NH;
#pragma unroll
    for (int mt = 0; mt < 2; mt++) {
#pragma unroll
        for (int i = 0; i < 2; i++) {
            int r = wm + mt * 16 + lr + i * 8;
            float inv = 1.0f / l_s[r];
            size_t rowp = (size_t)(bb * S + qt * BQ + r) * DOUT + h * HD;
#pragma unroll
            for (int nt = 0; nt < 4; nt++) {
                int c = wn + nt * 8 + lc * 2;
                *reinterpret_cast<float2*>(&ctx[rowp + c]) =
                    make_float2(acc_o[mt][nt][i * 2 + 0] * inv,
                                acc_o[mt][nt][i * 2 + 1] * inv);
            }
        }
    }
}

}  // namespace

extern "C" void kernel_launch(void* const* d_in, const int* in_sizes, int n_in,
                              void* d_out, int out_size)
{
    (void)in_sizes; (void)n_in; (void)out_size;
    const float* x  = (const float*)d_in[0];
    const float* Wq = (const float*)d_in[1];
    const float* Wk = (const float*)d_in[2];
    const float* Wv = (const float*)d_in[3];
    const float* Wo = (const float*)d_in[4];
    const float* bo = (const float*)d_in[5];
    float* out = (float*)d_out;

    float *qp, *kp, *vp, *cp;
    cudaGetSymbolAddress((void**)&qp, g_q);
    cudaGetSymbolAddress((void**)&kp, g_k);
    cudaGetSymbolAddress((void**)&vp, g_v);
    cudaGetSymbolAddress((void**)&cp, g_ctx);

    cudaFuncSetAttribute(gemm_tf32_kernel,
                         cudaFuncAttributeMaxDynamicSharedMemorySize,
                         (int)GEMM_SMEM);
    cudaFuncSetAttribute(attn_kernel,
                         cudaFuncAttributeMaxDynamicSharedMemorySize,
                         (int)ATTN_SMEM);

    dim3 gemm_grid(DOUT / GBN, M / GBM);   // (16, 64)

    gemm_tf32_kernel<<<gemm_grid, 256, GEMM_SMEM>>>(x, Wq, qp, nullptr, DIN, DOUT, 1);
    gemm_tf32_kernel<<<gemm_grid, 256, GEMM_SMEM>>>(x, Wk, kp, nullptr, DIN, DOUT, 1);
    gemm_tf32_kernel<<<gemm_grid, 256, GEMM_SMEM>>>(x, Wv, vp, nullptr, DIN, DOUT, 1);

    dim3 attn_grid(S / BQ, B * NH);        // (16, 64)
    attn_kernel<<<attn_grid, 256, ATTN_SMEM>>>(qp, kp, vp, cp);

    gemm_tf32_kernel<<<gemm_grid, 256, GEMM_SMEM>>>(cp, Wo, out, bo, DOUT, DOUT, 0);
}

// round 6
// speedup vs baseline: 1.8288x; 1.0743x over previous
#include <cuda_runtime.h>
#include <math.h>

namespace {

constexpr int B    = 4;
constexpr int S    = 2048;
constexpr int DIN  = 1024;
constexpr int DOUT = 1024;
constexpr int NH   = 16;
constexpr int HD   = 64;
constexpr int M    = B * S;            // 8192 rows

// ---- scratch (static device memory: allowed) ----
__device__ float g_q[(size_t)B * NH * S * HD];    // [B,H,S,HD]
__device__ float g_k[(size_t)B * NH * S * HD];
__device__ float g_v[(size_t)B * NH * S * HD];
__device__ float g_ctx[(size_t)M * DOUT];         // [B*S, DOUT] (tf32-rounded)
__device__ float g_xc[(size_t)M * DIN];           // tf32-rounded x
__device__ float g_wq[(size_t)DOUT * DIN];
__device__ float g_wk[(size_t)DOUT * DIN];
__device__ float g_wv[(size_t)DOUT * DIN];
__device__ float g_wo[(size_t)DOUT * DOUT];

__device__ __forceinline__ unsigned f2tf32(float x) {
    unsigned u;
    asm("cvt.rna.tf32.f32 %0, %1;" : "=r"(u) : "f"(x));
    return u;
}
__device__ __forceinline__ float tf(float x) { return __uint_as_float(f2tf32(x)); }

__device__ __forceinline__ void mma_tf32(
    float& c0, float& c1, float& c2, float& c3,
    unsigned a0, unsigned a1, unsigned a2, unsigned a3,
    unsigned b0, unsigned b1)
{
    asm volatile(
        "mma.sync.aligned.m16n8k8.row.col.f32.tf32.tf32.f32 "
        "{%0,%1,%2,%3}, {%4,%5,%6,%7}, {%8,%9}, {%0,%1,%2,%3};"
        : "+f"(c0), "+f"(c1), "+f"(c2), "+f"(c3)
        : "r"(a0), "r"(a1), "r"(a2), "r"(a3), "r"(b0), "r"(b1));
}

// ============================================================
// tf32 rounding pre-pass (rna; truncation would bias ~1e-3)
// ============================================================
__global__ __launch_bounds__(256) void cvt_tf32_kernel(
    const float* __restrict__ src, float* __restrict__ dst, int n4)
{
    int i = blockIdx.x * 256 + threadIdx.x;
    if (i < n4) {
        float4 v = reinterpret_cast<const float4*>(src)[i];
        v.x = tf(v.x); v.y = tf(v.y); v.z = tf(v.z); v.w = tf(v.w);
        reinterpret_cast<float4*>(dst)[i] = v;
    }
}

// ============================================================
// TF32 GEMM v2: inputs pre-rounded, float4 smem stores, no cvt.
// Block tile 128x64, BK=32; 8 warps 4(m)x2(n), warp tile 32x32.
// Optional fused-QKV: pass 3 W/C pointers, blockIdx.z selects.
// ============================================================
constexpr int GBM = 128, GBN = 64, GBK = 32, GPAD = 36;
constexpr size_t GEMM_SMEM = (size_t)(2 * GBM * GPAD + 2 * GBN * GPAD) * sizeof(float);

__device__ __forceinline__ void gemm_body(
    const float* __restrict__ A, const float* __restrict__ W,
    float* __restrict__ C, const float* __restrict__ bias,
    int K, int N, int head_layout, float* sm)
{
    float* sA = sm;
    float* sW = sm + 2 * GBM * GPAD;

    const int tid  = threadIdx.x;
    const int m0   = blockIdx.y * GBM;
    const int n0   = blockIdx.x * GBN;
    const int warp = tid >> 5, lane = tid & 31;
    const int wm = (warp >> 1) * 32;
    const int wn = (warp & 1) * 32;
    const int lr = lane >> 2, lc = lane & 3;

    float4 ra[4], rw[2];

    auto load_tile = [&](int k0) {
#pragma unroll
        for (int p = 0; p < 4; p++) {
            int idx = p * 256 + tid;
            int row = idx >> 3, c4 = (idx & 7) << 2;
            ra[p] = *reinterpret_cast<const float4*>(A + (size_t)(m0 + row) * K + k0 + c4);
        }
#pragma unroll
        for (int p = 0; p < 2; p++) {
            int idx = p * 256 + tid;
            int row = idx >> 3, c4 = (idx & 7) << 2;
            rw[p] = *reinterpret_cast<const float4*>(W + (size_t)(n0 + row) * K + k0 + c4);
        }
    };
    auto store_tile = [&](int buf) {
        float* dA = sA + buf * GBM * GPAD;
        float* dW = sW + buf * GBN * GPAD;
#pragma unroll
        for (int p = 0; p < 4; p++) {
            int idx = p * 256 + tid;
            int row = idx >> 3, c4 = (idx & 7) << 2;
            *reinterpret_cast<float4*>(&dA[row * GPAD + c4]) = ra[p];
        }
#pragma unroll
        for (int p = 0; p < 2; p++) {
            int idx = p * 256 + tid;
            int row = idx >> 3, c4 = (idx & 7) << 2;
            *reinterpret_cast<float4*>(&dW[row * GPAD + c4]) = rw[p];
        }
    };

    float acc[2][4][4] = {};

    load_tile(0);
    store_tile(0);
    const int NIT = K / GBK;
    for (int it = 0; it < NIT; ++it) {
        __syncthreads();
        if (it + 1 < NIT) load_tile((it + 1) * GBK);

        const float* bA = sA + (it & 1) * GBM * GPAD;
        const float* bW = sW + (it & 1) * GBN * GPAD;
#pragma unroll
        for (int kk = 0; kk < GBK; kk += 8) {
            unsigned af[2][4], bf[4][2];
#pragma unroll
            for (int mt = 0; mt < 2; mt++) {
                int r = wm + mt * 16 + lr;
                af[mt][0] = __float_as_uint(bA[r * GPAD + kk + lc]);
                af[mt][1] = __float_as_uint(bA[(r + 8) * GPAD + kk + lc]);
                af[mt][2] = __float_as_uint(bA[r * GPAD + kk + lc + 4]);
                af[mt][3] = __float_as_uint(bA[(r + 8) * GPAD + kk + lc + 4]);
            }
#pragma unroll
            for (int nt = 0; nt < 4; nt++) {
                int c = wn + nt * 8 + lr;
                bf[nt][0] = __float_as_uint(bW[c * GPAD + kk + lc]);
                bf[nt][1] = __float_as_uint(bW[c * GPAD + kk + lc + 4]);
            }
#pragma unroll
            for (int mt = 0; mt < 2; mt++)
#pragma unroll
                for (int nt = 0; nt < 4; nt++)
                    mma_tf32(acc[mt][nt][0], acc[mt][nt][1], acc[mt][nt][2], acc[mt][nt][3],
                             af[mt][0], af[mt][1], af[mt][2], af[mt][3],
                             bf[nt][0], bf[nt][1]);
        }
        if (it + 1 < NIT) store_tile((it + 1) & 1);
    }

#pragma unroll
    for (int mt = 0; mt < 2; mt++) {
#pragma unroll
        for (int i = 0; i < 2; i++) {
            int m = m0 + wm + mt * 16 + lr + i * 8;
#pragma unroll
            for (int nt = 0; nt < 4; nt++) {
                int n = n0 + wn + nt * 8 + lc * 2;
                float v0 = acc[mt][nt][i * 2 + 0];
                float v1 = acc[mt][nt][i * 2 + 1];
                if (bias) { v0 += bias[n]; v1 += bias[n + 1]; }
                if (!head_layout) {
                    *reinterpret_cast<float2*>(&C[(size_t)m * N + n]) = make_float2(v0, v1);
                } else {
                    int h = n >> 6, d = n & 63;
                    int bb = m >> 11, ss = m & 2047;
                    *reinterpret_cast<float2*>(
                        &C[(((size_t)(bb * NH + h) * S) + ss) * HD + d]) = make_float2(v0, v1);
                }
            }
        }
    }
}

__global__ __launch_bounds__(256) void qkv_gemm_kernel(
    const float* __restrict__ A,
    const float* __restrict__ Wq, const float* __restrict__ Wk, const float* __restrict__ Wv,
    float* __restrict__ q, float* __restrict__ k, float* __restrict__ v)
{
    extern __shared__ float sm[];
    const int z = blockIdx.z;
    const float* W = (z == 0) ? Wq : (z == 1) ? Wk : Wv;
    float* C       = (z == 0) ? q  : (z == 1) ? k  : v;
    gemm_body(A, W, C, nullptr, DIN, DOUT, 1, sm);
}

__global__ __launch_bounds__(256) void out_gemm_kernel(
    const float* __restrict__ A, const float* __restrict__ W,
    float* __restrict__ C, const float* __restrict__ bias)
{
    extern __shared__ float sm[];
    gemm_body(A, W, C, bias, DOUT, DOUT, 0, sm);
}

// ============================================================
// Causal flash attention (round-5 version, ctx written tf32-rounded)
// BQ=128, BKV=64, in-register softmax (exp2 domain).
// ============================================================
constexpr int BQ  = 128;
constexpr int BKV = 64;
constexpr int PAD = 68;
constexpr float LOG2E = 1.4426950408889634f;
constexpr size_t ATTN_SMEM = (size_t)(BQ + BKV + BKV + BQ) * PAD * sizeof(float); // 104448

__global__ __launch_bounds__(256) void attn_kernel(
    const float* __restrict__ Q, const float* __restrict__ Kp,
    const float* __restrict__ Vp, float* __restrict__ ctx)
{
    extern __shared__ float sm[];
    float (*Qs)[PAD] = reinterpret_cast<float(*)[PAD]>(sm);
    float (*Ks)[PAD] = reinterpret_cast<float(*)[PAD]>(sm + BQ * PAD);
    float (*Vs)[PAD] = reinterpret_cast<float(*)[PAD]>(sm + (BQ + BKV) * PAD);
    float (*Ps)[PAD] = reinterpret_cast<float(*)[PAD]>(sm + (BQ + 2 * BKV) * PAD);

    __shared__ float m_s[BQ], l_s[BQ];
    __shared__ float pmax[BQ][2], psum[BQ][2];

    const int tid  = threadIdx.x;
    const int warp = tid >> 5, lane = tid & 31;
    const int wm = (warp >> 1) * 32;
    const int wn = (warp & 1) * 32;
    const int wi = warp & 1;
    const int lr = lane >> 2, lc = lane & 3;
    const int qt = blockIdx.x;
    const int bh = blockIdx.y;

    const float* qb = Q  + (size_t)bh * S * HD + (size_t)qt * BQ * HD;
    const float* kb = Kp + (size_t)bh * S * HD;
    const float* vb = Vp + (size_t)bh * S * HD;

    const float qscale = 0.125f * LOG2E;
    for (int i = tid; i < BQ * HD / 4; i += 256) {
        int row = i >> 4;
        int c4  = (i & 15) << 2;
        float4 v = *reinterpret_cast<const float4*>(qb + row * HD + c4);
        Qs[row][c4 + 0] = tf(v.x * qscale);
        Qs[row][c4 + 1] = tf(v.y * qscale);
        Qs[row][c4 + 2] = tf(v.z * qscale);
        Qs[row][c4 + 3] = tf(v.w * qscale);
    }
    if (tid < BQ) { m_s[tid] = -1e30f; l_s[tid] = 0.f; }

    float acc_o[2][4][4] = {};
    __syncthreads();

    const int NKT = 2 * qt + 2;
    for (int kt = 0; kt < NKT; kt++) {
        const float* kp_ = kb + (size_t)kt * BKV * HD;
        const float* vp_ = vb + (size_t)kt * BKV * HD;
        for (int i = tid; i < BKV * HD / 4; i += 256) {
            int row = i >> 4, c4 = (i & 15) << 2;
            float4 vk = *reinterpret_cast<const float4*>(kp_ + row * HD + c4);
            Ks[row][c4 + 0] = tf(vk.x); Ks[row][c4 + 1] = tf(vk.y);
            Ks[row][c4 + 2] = tf(vk.z); Ks[row][c4 + 3] = tf(vk.w);
            float4 vv = *reinterpret_cast<const float4*>(vp_ + row * HD + c4);
            Vs[row][c4 + 0] = tf(vv.x); Vs[row][c4 + 1] = tf(vv.y);
            Vs[row][c4 + 2] = tf(vv.z); Vs[row][c4 + 3] = tf(vv.w);
        }
        __syncthreads();

        float acc_s[2][4][4] = {};
#pragma unroll
        for (int kk = 0; kk < HD; kk += 8) {
            unsigned af[2][4], bf[4][2];
#pragma unroll
            for (int mt = 0; mt < 2; mt++) {
                int r = wm + mt * 16 + lr;
                af[mt][0] = __float_as_uint(Qs[r][kk + lc]);
                af[mt][1] = __float_as_uint(Qs[r + 8][kk + lc]);
                af[mt][2] = __float_as_uint(Qs[r][kk + lc + 4]);
                af[mt][3] = __float_as_uint(Qs[r + 8][kk + lc + 4]);
            }
#pragma unroll
            for (int nt = 0; nt < 4; nt++) {
                int c = wn + nt * 8 + lr;
                bf[nt][0] = __float_as_uint(Ks[c][kk + lc]);
                bf[nt][1] = __float_as_uint(Ks[c][kk + lc + 4]);
            }
#pragma unroll
            for (int mt = 0; mt < 2; mt++)
#pragma unroll
                for (int nt = 0; nt < 4; nt++)
                    mma_tf32(acc_s[mt][nt][0], acc_s[mt][nt][1],
                             acc_s[mt][nt][2], acc_s[mt][nt][3],
                             af[mt][0], af[mt][1], af[mt][2], af[mt][3],
                             bf[nt][0], bf[nt][1]);
        }

        if (kt >= 2 * qt) {
            int cbase = kt * BKV - qt * BQ;
#pragma unroll
            for (int mt = 0; mt < 2; mt++) {
                int r0 = wm + mt * 16 + lr;
#pragma unroll
                for (int nt = 0; nt < 4; nt++) {
                    int c0 = cbase + wn + nt * 8 + 2 * lc;
                    if (c0 > r0)         acc_s[mt][nt][0] = -1e30f;
                    if (c0 + 1 > r0)     acc_s[mt][nt][1] = -1e30f;
                    if (c0 > r0 + 8)     acc_s[mt][nt][2] = -1e30f;
                    if (c0 + 1 > r0 + 8) acc_s[mt][nt][3] = -1e30f;
                }
            }
        }

#pragma unroll
        for (int mt = 0; mt < 2; mt++) {
            float m0 = -1e30f, m1 = -1e30f;
#pragma unroll
            for (int nt = 0; nt < 4; nt++) {
                m0 = fmaxf(m0, fmaxf(acc_s[mt][nt][0], acc_s[mt][nt][1]));
                m1 = fmaxf(m1, fmaxf(acc_s[mt][nt][2], acc_s[mt][nt][3]));
            }
            m0 = fmaxf(m0, __shfl_xor_sync(0xffffffffu, m0, 1));
            m0 = fmaxf(m0, __shfl_xor_sync(0xffffffffu, m0, 2));
            m1 = fmaxf(m1, __shfl_xor_sync(0xffffffffu, m1, 1));
            m1 = fmaxf(m1, __shfl_xor_sync(0xffffffffu, m1, 2));
            if (lc == 0) {
                pmax[wm + mt * 16 + lr][wi] = m0;
                pmax[wm + mt * 16 + lr + 8][wi] = m1;
            }
        }
        __syncthreads();

        float alpha[2][2], mxv[2][2];
#pragma unroll
        for (int mt = 0; mt < 2; mt++) {
#pragma unroll
            for (int i = 0; i < 2; i++) {
                int r = wm + mt * 16 + lr + i * 8;
                float mo = m_s[r];
                float mx = fmaxf(mo, fmaxf(pmax[r][0], pmax[r][1]));
                mxv[mt][i] = mx;
                alpha[mt][i] = exp2f(mo - mx);
                float sum = 0.f;
#pragma unroll
                for (int nt = 0; nt < 4; nt++) {
                    float p0 = tf(exp2f(acc_s[mt][nt][i * 2 + 0] - mx));
                    float p1 = tf(exp2f(acc_s[mt][nt][i * 2 + 1] - mx));
                    sum += p0 + p1;
                    *reinterpret_cast<float2*>(&Ps[r][wn + nt * 8 + 2 * lc]) =
                        make_float2(p0, p1);
                }
                sum += __shfl_xor_sync(0xffffffffu, sum, 1);
                sum += __shfl_xor_sync(0xffffffffu, sum, 2);
                if (lc == 0) psum[r][wi] = sum;
            }
        }
        __syncthreads();

        if (wi == 0 && lc == 0) {
#pragma unroll
            for (int mt = 0; mt < 2; mt++)
#pragma unroll
                for (int i = 0; i < 2; i++) {
                    int r = wm + mt * 16 + lr + i * 8;
                    l_s[r] = l_s[r] * alpha[mt][i] + psum[r][0] + psum[r][1];
                    m_s[r] = mxv[mt][i];
                }
        }
#pragma unroll
        for (int mt = 0; mt < 2; mt++)
#pragma unroll
            for (int nt = 0; nt < 4; nt++) {
                acc_o[mt][nt][0] *= alpha[mt][0]; acc_o[mt][nt][1] *= alpha[mt][0];
                acc_o[mt][nt][2] *= alpha[mt][1]; acc_o[mt][nt][3] *= alpha[mt][1];
            }
#pragma unroll
        for (int kk = 0; kk < BKV; kk += 8) {
            unsigned af[2][4], bf[4][2];
#pragma unroll
            for (int mt = 0; mt < 2; mt++) {
                int r = wm + mt * 16 + lr;
                af[mt][0] = __float_as_uint(Ps[r][kk + lc]);
                af[mt][1] = __float_as_uint(Ps[r + 8][kk + lc]);
                af[mt][2] = __float_as_uint(Ps[r][kk + lc + 4]);
                af[mt][3] = __float_as_uint(Ps[r + 8][kk + lc + 4]);
            }
#pragma unroll
            for (int nt = 0; nt < 4; nt++) {
                int c = wn + nt * 8 + lr;
                bf[nt][0] = __float_as_uint(Vs[kk + lc][c]);
                bf[nt][1] = __float_as_uint(Vs[kk + lc + 4][c]);
            }
#pragma unroll
            for (int mt = 0; mt < 2; mt++)
#pragma unroll
                for (int nt = 0; nt < 4; nt++)
                    mma_tf32(acc_o[mt][nt][0], acc_o[mt][nt][1],
                             acc_o[mt][nt][2], acc_o[mt][nt][3],
                             af[mt][0], af[mt][1], af[mt][2], af[mt][3],
                             bf[nt][0], bf[nt][1]);
        }
        __syncthreads();
    }

    // epilogue: normalize, round to tf32 (feeds the Wo GEMM), write ctx
    const int h  = bh % NH;
    const int bb = bh / NH;
#pragma unroll
    for (int mt = 0; mt < 2; mt++) {
#pragma unroll
        for (int i = 0; i < 2; i++) {
            int r = wm + mt * 16 + lr + i * 8;
            float inv = 1.0f / l_s[r];
            size_t rowp = (size_t)(bb * S + qt * BQ + r) * DOUT + h * HD;
#pragma unroll
            for (int nt = 0; nt < 4; nt++) {
                int c = wn + nt * 8 + lc * 2;
                *reinterpret_cast<float2*>(&ctx[rowp + c]) =
                    make_float2(tf(acc_o[mt][nt][i * 2 + 0] * inv),
                                tf(acc_o[mt][nt][i * 2 + 1] * inv));
            }
        }
    }
}

}  // namespace

extern "C" void kernel_launch(void* const* d_in, const int* in_sizes, int n_in,
                              void* d_out, int out_size)
{
    (void)in_sizes; (void)n_in; (void)out_size;
    const float* x  = (const float*)d_in[0];
    const float* Wq = (const float*)d_in[1];
    const float* Wk = (const float*)d_in[2];
    const float* Wv = (const float*)d_in[3];
    const float* Wo = (const float*)d_in[4];
    const float* bo = (const float*)d_in[5];
    float* out = (float*)d_out;

    float *qp, *kp, *vp, *cp, *xc, *wq, *wk, *wv, *wo;
    cudaGetSymbolAddress((void**)&qp, g_q);
    cudaGetSymbolAddress((void**)&kp, g_k);
    cudaGetSymbolAddress((void**)&vp, g_v);
    cudaGetSymbolAddress((void**)&cp, g_ctx);
    cudaGetSymbolAddress((void**)&xc, g_xc);
    cudaGetSymbolAddress((void**)&wq, g_wq);
    cudaGetSymbolAddress((void**)&wk, g_wk);
    cudaGetSymbolAddress((void**)&wv, g_wv);
    cudaGetSymbolAddress((void**)&wo, g_wo);

    cudaFuncSetAttribute(qkv_gemm_kernel,
                         cudaFuncAttributeMaxDynamicSharedMemorySize, (int)GEMM_SMEM);
    cudaFuncSetAttribute(out_gemm_kernel,
                         cudaFuncAttributeMaxDynamicSharedMemorySize, (int)GEMM_SMEM);
    cudaFuncSetAttribute(attn_kernel,
                         cudaFuncAttributeMaxDynamicSharedMemorySize, (int)ATTN_SMEM);

    // ---- tf32 rounding pre-pass ----
    {
        int nx = M * DIN / 4;               // 2097152
        cvt_tf32_kernel<<<(nx + 255) / 256, 256>>>(x, xc, nx);
        int nw = DOUT * DIN / 4;            // 262144
        cvt_tf32_kernel<<<(nw + 255) / 256, 256>>>(Wq, wq, nw);
        cvt_tf32_kernel<<<(nw + 255) / 256, 256>>>(Wk, wk, nw);
        cvt_tf32_kernel<<<(nw + 255) / 256, 256>>>(Wv, wv, nw);
        cvt_tf32_kernel<<<(nw + 255) / 256, 256>>>(Wo, wo, nw);
    }

    // ---- fused QKV projections ----
    dim3 qkv_grid(DOUT / GBN, M / GBM, 3);  // (16, 64, 3)
    qkv_gemm_kernel<<<qkv_grid, 256, GEMM_SMEM>>>(xc, wq, wk, wv, qp, kp, vp);

    // ---- attention ----
    dim3 attn_grid(S / BQ, B * NH);         // (16, 64)
    attn_kernel<<<attn_grid, 256, ATTN_SMEM>>>(qp, kp, vp, cp);

    // ---- output projection ----
    dim3 out_grid(DOUT / GBN, M / GBM);     // (16, 64)
    out_gemm_kernel<<<out_grid, 256, GEMM_SMEM>>>(cp, wo, out, bo);
}